// round 8
// baseline (speedup 1.0000x reference)
#include <cuda_runtime.h>

#define TT 1024
#define NT 512
#define DD 263
#define SD 68      // scratch depth (67 used, padded)
#define MAXB 256

// transposed motion: scratch[b][d][t], d in [0,67)
__device__ float g_scratch[(long)MAXB * SD * TT];

// group id per joint: 0=ROOT_AND_SPINE(n=6), 1=FEET(n=4), 2=HANDS(n=8), 3=OTHER(n=4)
__constant__ int c_grp[22] = {0,3,3,0,3,3,0,1,1,0,1,1,0,2,2,0,2,2,2,2,2,2};

// ---------------- transpose kernel: motion[b][t][d<67] -> g_scratch[b][d][t] ----------------
__global__ __launch_bounds__(256)
void transpose_kernel(const float* __restrict__ motion)
{
    __shared__ float tile[32][33];
    const int bx = blockIdx.x;           // t tile (0..31)
    const int by = blockIdx.y;           // d tile (0..2)
    const int b  = blockIdx.z;
    const int tx = threadIdx.x, ty = threadIdx.y;

    const int d0 = by * 32;
    const int t0 = bx * 32;

    #pragma unroll
    for (int i = 0; i < 4; i++) {
        int tr = ty + 8 * i;             // row within tile (t offset)
        int d = d0 + tx;
        if (d < 67) {
            tile[tr][tx] = motion[((long)b * TT + (t0 + tr)) * DD + d];
        }
    }
    __syncthreads();
    #pragma unroll
    for (int i = 0; i < 4; i++) {
        int dr = d0 + ty + 8 * i;        // output d
        int t = t0 + tx;
        if (dr < 67) {
            g_scratch[((long)b * SD + dr) * TT + t] = tile[tx][ty + 8 * i];
        }
    }
}

// ---------------- helpers ----------------
__device__ __forceinline__ float warpInclScan(float v) {
    int lane = threadIdx.x & 31;
    #pragma unroll
    for (int o = 1; o < 32; o <<= 1) {
        float n = __shfl_up_sync(0xffffffffu, v, o);
        if (lane >= o) v += n;
    }
    return v;
}

__device__ __forceinline__ float blockInclScan(float v, float* s_w) {
    int lane = threadIdx.x & 31, wid = threadIdx.x >> 5;
    float x = warpInclScan(v);
    if (lane == 31) s_w[wid] = x;
    __syncthreads();
    if (wid == 0) { float y = s_w[lane]; y = warpInclScan(y); s_w[lane] = y; }
    __syncthreads();
    float off = (wid > 0) ? s_w[wid - 1] : 0.0f;
    return x + off;
}

__device__ __forceinline__ void blockInclScan2(float& a, float& b, float* swa, float* swb) {
    int lane = threadIdx.x & 31, wid = threadIdx.x >> 5;
    float xa = warpInclScan(a), xb = warpInclScan(b);
    if (lane == 31) { swa[wid] = xa; swb[wid] = xb; }
    __syncthreads();
    if (wid == 0) {
        float ya = swa[lane], yb = swb[lane];
        ya = warpInclScan(ya); yb = warpInclScan(yb);
        swa[lane] = ya; swb[lane] = yb;
    }
    __syncthreads();
    a = xa + ((wid > 0) ? swa[wid - 1] : 0.0f);
    b = xb + ((wid > 0) ? swb[wid - 1] : 0.0f);
}

__device__ __forceinline__ float blockReduceMax(float v, float* s_red) {
    int t = threadIdx.x;
    #pragma unroll
    for (int o = 16; o > 0; o >>= 1) v = fmaxf(v, __shfl_xor_sync(0xffffffffu, v, o));
    if ((t & 31) == 0) s_red[t >> 5] = v;
    __syncthreads();
    if (t < 16) {
        float w = s_red[t];
        #pragma unroll
        for (int o = 8; o > 0; o >>= 1) w = fmaxf(w, __shfl_xor_sync(0xffffu, w, o));
        if (t == 0) s_red[0] = w;
    }
    __syncthreads();
    float r = s_red[0];
    __syncthreads();
    return r;
}

__device__ __forceinline__ float blockReduceSumF(float v, float* s_red) {
    int t = threadIdx.x;
    #pragma unroll
    for (int o = 16; o > 0; o >>= 1) v += __shfl_xor_sync(0xffffffffu, v, o);
    if ((t & 31) == 0) s_red[t >> 5] = v;
    __syncthreads();
    if (t < 16) {
        float w = s_red[t];
        #pragma unroll
        for (int o = 8; o > 0; o >>= 1) w += __shfl_xor_sync(0xffffu, w, o);
        if (t == 0) s_red[0] = w;
    }
    __syncthreads();
    float r = s_red[0];
    __syncthreads();
    return r;
}

__device__ __forceinline__ int blockReduceSumI(int v, int* s_red) {
    int t = threadIdx.x;
    #pragma unroll
    for (int o = 16; o > 0; o >>= 1) v += __shfl_xor_sync(0xffffffffu, v, o);
    if ((t & 31) == 0) s_red[t >> 5] = v;
    __syncthreads();
    if (t < 16) {
        int w = s_red[t];
        #pragma unroll
        for (int o = 8; o > 0; o >>= 1) w += __shfl_xor_sync(0xffffu, w, o);
        if (t == 0) s_red[0] = w;
    }
    __syncthreads();
    int r = s_red[0];
    __syncthreads();
    return r;
}

__device__ __forceinline__ void rotY(float qc, float qs, float wx, float wz,
                                     float& ox, float& oz) {
    float uvx = (-qs) * wz;
    float uvz = qs * wx;
    float uuvx = (-qs) * uvz;
    float uuvz = qs * uvx;
    ox = wx + 2.0f * (qc * uvx + uuvx);
    oz = wz + 2.0f * (qc * uvz + uuvz);
}

__device__ __forceinline__ float energyFast(
    float px, float py, float pz,
    float q1x, float q1y, float q1z,
    float q2x, float q2y, float q2z,
    float q3x, float q3y, float q3z)
{
    float v3x = px - q1x,  v3y = py - q1y,  v3z = pz - q1z;
    float v2x = q1x - q2x, v2y = q1y - q2y, v2z = q1z - q2z;
    float v1x = q2x - q3x, v1y = q2y - q3y, v1z = q2z - q3z;
    float a3x = v3x - v2x, a3y = v3y - v2y, a3z = v3z - v2z;
    float a2x = v2x - v1x, a2y = v2y - v1y, a2z = v2z - v1z;
    float jx  = a3x - a2x, jy  = a3y - a2y, jz  = a3z - a2z;
    float nv = sqrtf(((v3x * v3x + v3y * v3y) + v3z * v3z) + 1e-12f);
    float na = sqrtf(((a3x * a3x + a3y * a3y) + a3z * a3z) + 1e-12f);
    float nj = sqrtf(((jx * jx + jy * jy) + jz * jz) + 1e-12f);
    return (nv + 0.6f * na) + 0.35f * nj;
}

__device__ __forceinline__ float energyGuard(int tau,
    float px, float py, float pz,
    float q1x, float q1y, float q1z,
    float q2x, float q2y, float q2z,
    float q3x, float q3y, float q3z)
{
    float v3x = (tau >= 1) ? px - q1x : 0.f, v3y = (tau >= 1) ? py - q1y : 0.f, v3z = (tau >= 1) ? pz - q1z : 0.f;
    float v2x = (tau >= 2) ? q1x - q2x : 0.f, v2y = (tau >= 2) ? q1y - q2y : 0.f, v2z = (tau >= 2) ? q1z - q2z : 0.f;
    float v1x = (tau >= 3) ? q2x - q3x : 0.f, v1y = (tau >= 3) ? q2y - q3y : 0.f, v1z = (tau >= 3) ? q2z - q3z : 0.f;
    float a3x = (tau >= 1) ? v3x - v2x : 0.f, a3y = (tau >= 1) ? v3y - v2y : 0.f, a3z = (tau >= 1) ? v3z - v2z : 0.f;
    float a2x = (tau >= 2) ? v2x - v1x : 0.f, a2y = (tau >= 2) ? v2y - v1y : 0.f, a2z = (tau >= 2) ? v2z - v1z : 0.f;
    float jx  = (tau >= 1) ? a3x - a2x : 0.f, jy  = (tau >= 1) ? a3y - a2y : 0.f, jz  = (tau >= 1) ? a3z - a2z : 0.f;
    float nv = sqrtf(((v3x * v3x + v3y * v3y) + v3z * v3z) + 1e-12f);
    float na = sqrtf(((a3x * a3x + a3y * a3y) + a3z * a3z) + 1e-12f);
    float nj = sqrtf(((jx * jx + jy * jy) + jz * jz) + 1e-12f);
    return (nv + 0.6f * na) + 0.35f * nj;
}

__device__ __forceinline__ float wrapPi(float hd) {
    const float TWO_PI = 6.28318530717958647692f;
    const float INV_TWO_PI = 0.15915494309189533577f;
    return hd - TWO_PI * rintf(hd * INV_TWO_PI);
}

__global__ __launch_bounds__(NT, 2)
void msal_kernel(const int* __restrict__ mask,
                 float* __restrict__ out,
                 int Bn)
{
    __shared__ float2 s_px[2][NT], s_py[2][NT], s_pz[2][NT];
    __shared__ float4 s_rth[NT];
    __shared__ float2 s_sal[NT];
    __shared__ float  s_srt[2][TT];
    __shared__ float  s_redf[32];
    __shared__ int    s_redi[32];
    __shared__ float  s_w1[32], s_w2[32];

    const int tid = threadIdx.x;
    const int b = blockIdx.x;
    const int t0 = 2 * tid, t1 = t0 + 1;
    const float* scr = g_scratch + (long)b * SD * TT;   // scr[d*TT + t]
    const int2 mvp = ((const int2*)(mask + (long)b * TT))[tid];
    const int mv0 = mvp.x, mv1 = mvp.y;
    const float mf0 = mv0 ? 1.0f : 0.0f;
    const float mf1 = mv1 ? 1.0f : 0.0f;

    // ---- ang: exclusive cumsum of rot_vel ----
    const float2 rvp = ((const float2*)(scr + 0 * TT))[tid];
    const float rv0 = rvp.x, rv1 = rvp.y;
    float ang0, ang1;
    {
        float pair = rv0 + rv1;
        float incl = blockInclScan(pair, s_w1);
        float excl = incl - pair;
        ang0 = excl;
        ang1 = excl + rv0;
    }
    const float qc0 = cosf(ang0), qs0 = sinf(ang0);
    const float qc1 = cosf(ang1), qs1 = sinf(ang1);

    // ---- root xz steps rotated, then inclusive cumsum ----
    float sx0 = 0.f, sz0 = 0.f, sx1, sz1;
    {
        float vx0 = 0.f, vz0 = 0.f;
        if (t0 > 0) { vx0 = scr[1 * TT + t0 - 1]; vz0 = scr[2 * TT + t0 - 1]; }
        float vx1 = scr[1 * TT + t0], vz1 = scr[2 * TT + t0];
        rotY(qc0, qs0, vx0, vz0, sx0, sz0);
        rotY(qc1, qs1, vx1, vz1, sx1, sz1);
    }
    float rx0, rz0, rx1, rz1;
    {
        float pairx = sx0 + sx1, pairz = sz0 + sz1;
        __syncthreads();   // protect s_w reuse
        float ix = pairx, iz = pairz;
        blockInclScan2(ix, iz, s_w1, s_w2);
        float ex = ix - pairx, ez = iz - pairz;
        rx0 = ex + sx0;         rz0 = ez + sz0;
        rx1 = (ex + sx0) + sx1; rz1 = (ez + sz0) + sz1;
    }

    float h_t1;
    {
        float pv1x = rx1 - rx0, pv1z = rz1 - rz0;
        bool z = (fabsf(pv1x) < 1e-8f) && (fabsf(pv1z) < 1e-8f);
        h_t1 = atan2f(z ? 0.f : pv1z, z ? 1.f : pv1x);
    }
    s_rth[tid] = make_float4(rx1, rz1, h_t1, 0.f);

    // ---- group energies ----
    float S0a = 0.f, S1a = 0.f, S2a = 0.f, S3a = 0.f;
    float S0b = 0.f, S1b = 0.f, S2b = 0.f, S3b = 0.f;

    const float2 pyp = ((const float2*)(scr + 3 * TT))[tid];
    const float py0r = pyp.x, py1r = pyp.y;
    float wx0 = 0.f, wy0 = 0.f, wz0 = 0.f;
    float wx1 = 0.f, wy1 = 0.f, wz1 = 0.f;

    for (int j = 0; j < 22; j++) {
        const int buf = j & 1;
        float px0, py0, pz0, px1, py1, pz1;
        if (j == 0) {
            px0 = rx0; py0 = py0r; pz0 = rz0;
            px1 = rx1; py1 = py1r; pz1 = rz1;
        } else {
            float ax, az, bx, bz;
            rotY(qc0, qs0, wx0, wz0, ax, az);
            rotY(qc1, qs1, wx1, wz1, bx, bz);
            px0 = ax + rx0; py0 = wy0; pz0 = az + rz0;
            px1 = bx + rx1; py1 = wy1; pz1 = bz + rz1;
        }
        // prefetch next joint raw data (coalesced float2 loads from scratch)
        float nx0 = 0.f, ny0 = 0.f, nz0 = 0.f, nx1 = 0.f, ny1 = 0.f, nz1 = 0.f;
        if (j < 21) {
            const int d = 4 + 3 * j;   // d index of joint (j+1)'s x
            float2 X = ((const float2*)(scr + (long)d * TT))[tid];
            float2 Y = ((const float2*)(scr + (long)(d + 1) * TT))[tid];
            float2 Z = ((const float2*)(scr + (long)(d + 2) * TT))[tid];
            nx0 = X.x; nx1 = X.y;
            ny0 = Y.x; ny1 = Y.y;
            nz0 = Z.x; nz1 = Z.y;
        }
        s_px[buf][tid] = make_float2(px0, px1);
        s_py[buf][tid] = make_float2(py0, py1);
        s_pz[buf][tid] = make_float2(pz0, pz1);
        __syncthreads();

        float e0, e1;
        if (tid >= 2) {
            float2 Ax = s_px[buf][tid - 1], Ay = s_py[buf][tid - 1], Az = s_pz[buf][tid - 1];
            float2 Bx = s_px[buf][tid - 2], By = s_py[buf][tid - 2], Bz = s_pz[buf][tid - 2];
            e0 = energyFast(px0, py0, pz0,
                            Ax.y, Ay.y, Az.y,
                            Ax.x, Ay.x, Az.x,
                            Bx.y, By.y, Bz.y);
            e1 = energyFast(px1, py1, pz1,
                            px0, py0, pz0,
                            Ax.y, Ay.y, Az.y,
                            Ax.x, Ay.x, Az.x);
        } else {
            float2 Ax = make_float2(0.f, 0.f), Ay = Ax, Az = Ax;
            if (tid >= 1) { Ax = s_px[buf][tid - 1]; Ay = s_py[buf][tid - 1]; Az = s_pz[buf][tid - 1]; }
            e0 = energyGuard(t0, px0, py0, pz0,
                             Ax.y, Ay.y, Az.y,
                             Ax.x, Ay.x, Az.x,
                             0.f, 0.f, 0.f);
            e1 = energyGuard(t1, px1, py1, pz1,
                             px0, py0, pz0,
                             Ax.y, Ay.y, Az.y,
                             Ax.x, Ay.x, Az.x);
        }

        int g = c_grp[j];
        if      (g == 0) { S0a += e0; S0b += e1; }
        else if (g == 1) { S1a += e0; S1b += e1; }
        else if (g == 2) { S2a += e0; S2b += e1; }
        else             { S3a += e0; S3b += e1; }

        wx0 = nx0; wy0 = ny0; wz0 = nz0;
        wx1 = nx1; wy1 = ny1; wz1 = nz1;
    }

    float Ea = (((1.6f * (S0a / 6.0f) + 1.4f * (S1a / 4.0f)) + 1.2f * (S2a / 8.0f)) + 0.8f * (S3a / 4.0f));
    float Eb = (((1.6f * (S0b / 6.0f) + 1.4f * (S1b / 4.0f)) + 1.2f * (S2b / 8.0f)) + 0.8f * (S3b / 4.0f));

    // ---- turning ----
    float turn0, turn1;
    {
        float rxm1 = 0.f, rzm1 = 0.f, hprev = 0.f;
        if (tid >= 1) {
            float4 rr = s_rth[tid - 1];
            rxm1 = rr.x; rzm1 = rr.y; hprev = rr.z;
        }
        float pv0x = (tid >= 1) ? rx0 - rxm1 : 0.f;
        float pv0z = (tid >= 1) ? rz0 - rzm1 : 0.f;
        bool z = (fabsf(pv0x) < 1e-8f) && (fabsf(pv0z) < 1e-8f);
        float h_t0 = atan2f(z ? 0.f : pv0z, z ? 1.f : pv0x);
        float hd0 = (tid >= 1) ? h_t0 - hprev : 0.f;
        float hd1 = h_t1 - h_t0;
        float wr0 = wrapPi(hd0);
        float wr1 = wrapPi(hd1);
        float pv1x = rx1 - rx0, pv1z = rz1 - rz0;
        turn0 = fabsf(wr0) * sqrtf((pv0x * pv0x + pv0z * pv0z) + 1e-12f);
        turn1 = fabsf(wr1) * sqrtf((pv1x * pv1x + pv1z * pv1z) + 1e-12f);
    }

    float sal0 = (Ea + 1.6f * turn0) * mf0;
    float sal1 = (Eb + 1.6f * turn1) * mf1;

    // ---- normalize by row max ----
    float m = blockReduceMax(fmaxf(sal0, sal1), s_redf);
    m = fmaxf(m, 1e-6f);
    float salN0 = fminf(fmaxf(sal0 / m, 0.0f), 1.0f) * mf0;
    float salN1 = fminf(fmaxf(sal1 / m, 0.0f), 1.0f) * mf1;
    s_sal[tid] = make_float2(salN0, salN1);
    __syncthreads();

    // ---- local max suppression (window 5, pad 2) ----
    float2 L = (tid >= 1)      ? s_sal[tid - 1] : make_float2(-1.f, -1.f);
    float2 R = (tid < NT - 1)  ? s_sal[tid + 1] : make_float2(-1.f, -1.f);
    float lm0 = fmaxf(fmaxf(fmaxf(L.x, L.y), fmaxf(salN0, salN1)), R.x);
    float lm1 = fmaxf(fmaxf(fmaxf(L.y, salN0), fmaxf(salN1, R.x)), R.y);
    float probs0 = salN0 * ((salN0 >= lm0 - 1e-6f) ? 1.0f : 0.0f) * mf0;
    float probs1 = salN1 * ((salN1 >= lm1 - 1e-6f) ? 1.0f : 0.0f) * mf1;
    probs0 = fminf(fmaxf(probs0, 0.0f), 1.0f) * mf0;
    probs1 = fminf(fmaxf(probs1, 0.0f), 1.0f) * mf1;

    // ---- adaptive ST ----
    int n = blockReduceSumI((mv0 ? 1 : 0) + (mv1 ? 1 : 0), s_redi);
    float hv = (n > 0) ? 1.0f : 0.0f;
    int last = ((n > 1) ? n : 1) - 1;
    float ep0 = (t0 == 0 || t0 == last) ? hv : 0.0f;
    float ep1 = (t1 == last) ? hv : 0.0f;
    probs0 = fmaxf(probs0, ep0) * mf0;
    probs1 = fmaxf(probs1, ep1) * mf1;

    float nf = (float)((n > 1) ? n : 1);
    float asum = blockReduceSumF(probs0 * mf0 + probs1 * mf1, s_redf);
    float activity = asum / nf;
    float q = 0.85f + 0.1f * 0.5f - 0.1f * activity;
    q = fminf(fmaxf(q, 0.8f), 0.95f);
    float pos = q * (nf - 1.0f);
    float lof = floorf(pos), hif = ceilf(pos);
    int ilo = (int)lof, ihi = (int)hif;

    // ---- bitonic sort: 1024 elems, 2 per thread ----
    const int i0 = tid, i1 = tid + NT;
    float v0 = mv0 ? probs0 : 2.0f;
    float v1 = mv1 ? probs1 : 2.0f;
    int pb = 0;
    for (int k = 2; k <= TT; k <<= 1) {
        bool up0 = ((i0 & k) == 0);
        bool up1 = ((i1 & k) == 0);
        int j2 = k >> 1;
        if (j2 == NT) {
            float mn = fminf(v0, v1), mx = fmaxf(v0, v1);
            v0 = up0 ? mn : mx;
            v1 = up0 ? mx : mn;
            j2 = NT >> 1;
        }
        for (; j2 >= 32; j2 >>= 1) {
            s_srt[pb][i0] = v0; s_srt[pb][i1] = v1;
            __syncthreads();
            float p0 = s_srt[pb][i0 ^ j2];
            float p1 = s_srt[pb][i1 ^ j2];
            pb ^= 1;
            bool l0 = (i0 & j2) == 0, l1 = (i1 & j2) == 0;
            v0 = (l0 == up0) ? fminf(v0, p0) : fmaxf(v0, p0);
            v1 = (l1 == up1) ? fminf(v1, p1) : fmaxf(v1, p1);
        }
        for (; j2 >= 1; j2 >>= 1) {
            float p0 = __shfl_xor_sync(0xffffffffu, v0, j2);
            float p1 = __shfl_xor_sync(0xffffffffu, v1, j2);
            bool l0 = (i0 & j2) == 0, l1 = (i1 & j2) == 0;
            v0 = (l0 == up0) ? fminf(v0, p0) : fmaxf(v0, p0);
            v1 = (l1 == up1) ? fminf(v1, p1) : fmaxf(v1, p1);
        }
    }
    s_srt[pb][i0] = v0; s_srt[pb][i1] = v1;
    __syncthreads();
    float vlo = s_srt[pb][ilo], vhi = s_srt[pb][ihi];
    float cut = vlo + (pos - lof) * (vhi - vlo);

    float hard0, hard1;
    if (n > 0 && n <= 2)      { hard0 = mf0; hard1 = mf1; }
    else if (n > 2)           { hard0 = (probs0 >= cut) ? 1.0f : 0.0f;
                                hard1 = (probs1 >= cut) ? 1.0f : 0.0f; }
    else                      { hard0 = 0.0f; hard1 = 0.0f; }

    hard0 = fmaxf(hard0, ep0) * mf0;
    hard1 = fmaxf(hard1, ep1) * mf1;
    float pF0 = fmaxf(probs0, ep0) * mf0;
    float pF1 = fmaxf(probs1, ep1) * mf1;
    float st0 = ((hard0 + pF0) - pF0) * mf0;
    float st1 = ((hard1 + pF1) - pF1) * mf1;

    ((float2*)(out + (long)b * TT))[tid] = make_float2(pF0, pF1);
    ((float2*)(out + (long)Bn * TT + (long)b * TT))[tid] = make_float2(st0, st1);
}

extern "C" void kernel_launch(void* const* d_in, const int* in_sizes, int n_in,
                              void* d_out, int out_size) {
    const float* motion = (const float*)d_in[0];
    const int* mask = (const int*)d_in[1];
    float* out = (float*)d_out;
    int Bn = in_sizes[0] / (TT * DD);
    dim3 tgrid(TT / 32, 3, Bn);
    dim3 tblk(32, 8);
    transpose_kernel<<<tgrid, tblk>>>(motion);
    msal_kernel<<<Bn, NT>>>(mask, out, Bn);
}

// round 9
// speedup vs baseline: 1.1498x; 1.1498x over previous
#include <cuda_runtime.h>

#define TT 1024
#define NT 512
#define DD 263

// group id per joint: 0=ROOT_AND_SPINE(n=6), 1=FEET(n=4), 2=HANDS(n=8), 3=OTHER(n=4)
__constant__ int c_grp[22] = {0,3,3,0,3,3,0,1,1,0,1,1,0,2,2,0,2,2,2,2,2,2};

#define RAW_STRIDE 1026   // floats per plane row (pad 2 -> conflict-free f32 writes & f64 reads)

struct Smem {
    float  raw[9][RAW_STRIDE];      // staged d-planes
    float2 px[2][NT], py[2][NT], pz[2][NT];
    float4 rth[NT];
    float2 sal[NT];
    float  srt[2][TT];
    float  redf[32];
    int    redi[32];
    float  w1[32], w2[32];
};

__device__ __forceinline__ float warpInclScan(float v) {
    int lane = threadIdx.x & 31;
    #pragma unroll
    for (int o = 1; o < 32; o <<= 1) {
        float n = __shfl_up_sync(0xffffffffu, v, o);
        if (lane >= o) v += n;
    }
    return v;
}

__device__ __forceinline__ float blockInclScan(float v, float* s_w) {
    int lane = threadIdx.x & 31, wid = threadIdx.x >> 5;
    float x = warpInclScan(v);
    if (lane == 31) s_w[wid] = x;
    __syncthreads();
    if (wid == 0) { float y = s_w[lane]; y = warpInclScan(y); s_w[lane] = y; }
    __syncthreads();
    float off = (wid > 0) ? s_w[wid - 1] : 0.0f;
    return x + off;
}

__device__ __forceinline__ void blockInclScan2(float& a, float& b, float* swa, float* swb) {
    int lane = threadIdx.x & 31, wid = threadIdx.x >> 5;
    float xa = warpInclScan(a), xb = warpInclScan(b);
    if (lane == 31) { swa[wid] = xa; swb[wid] = xb; }
    __syncthreads();
    if (wid == 0) {
        float ya = swa[lane], yb = swb[lane];
        ya = warpInclScan(ya); yb = warpInclScan(yb);
        swa[lane] = ya; swb[lane] = yb;
    }
    __syncthreads();
    a = xa + ((wid > 0) ? swa[wid - 1] : 0.0f);
    b = xb + ((wid > 0) ? swb[wid - 1] : 0.0f);
}

__device__ __forceinline__ float blockReduceMax(float v, float* s_red) {
    int t = threadIdx.x;
    #pragma unroll
    for (int o = 16; o > 0; o >>= 1) v = fmaxf(v, __shfl_xor_sync(0xffffffffu, v, o));
    if ((t & 31) == 0) s_red[t >> 5] = v;
    __syncthreads();
    if (t < 16) {
        float w = s_red[t];
        #pragma unroll
        for (int o = 8; o > 0; o >>= 1) w = fmaxf(w, __shfl_xor_sync(0xffffu, w, o));
        if (t == 0) s_red[0] = w;
    }
    __syncthreads();
    float r = s_red[0];
    __syncthreads();
    return r;
}

__device__ __forceinline__ float blockReduceSumF(float v, float* s_red) {
    int t = threadIdx.x;
    #pragma unroll
    for (int o = 16; o > 0; o >>= 1) v += __shfl_xor_sync(0xffffffffu, v, o);
    if ((t & 31) == 0) s_red[t >> 5] = v;
    __syncthreads();
    if (t < 16) {
        float w = s_red[t];
        #pragma unroll
        for (int o = 8; o > 0; o >>= 1) w += __shfl_xor_sync(0xffffu, w, o);
        if (t == 0) s_red[0] = w;
    }
    __syncthreads();
    float r = s_red[0];
    __syncthreads();
    return r;
}

__device__ __forceinline__ int blockReduceSumI(int v, int* s_red) {
    int t = threadIdx.x;
    #pragma unroll
    for (int o = 16; o > 0; o >>= 1) v += __shfl_xor_sync(0xffffffffu, v, o);
    if ((t & 31) == 0) s_red[t >> 5] = v;
    __syncthreads();
    if (t < 16) {
        int w = s_red[t];
        #pragma unroll
        for (int o = 8; o > 0; o >>= 1) w += __shfl_xor_sync(0xffffu, w, o);
        if (t == 0) s_red[0] = w;
    }
    __syncthreads();
    int r = s_red[0];
    __syncthreads();
    return r;
}

__device__ __forceinline__ void rotY(float qc, float qs, float wx, float wz,
                                     float& ox, float& oz) {
    float uvx = (-qs) * wz;
    float uvz = qs * wx;
    float uuvx = (-qs) * uvz;
    float uuvz = qs * uvx;
    ox = wx + 2.0f * (qc * uvx + uuvx);
    oz = wz + 2.0f * (qc * uvz + uuvz);
}

__device__ __forceinline__ float energyFast(
    float px, float py, float pz,
    float q1x, float q1y, float q1z,
    float q2x, float q2y, float q2z,
    float q3x, float q3y, float q3z)
{
    float v3x = px - q1x,  v3y = py - q1y,  v3z = pz - q1z;
    float v2x = q1x - q2x, v2y = q1y - q2y, v2z = q1z - q2z;
    float v1x = q2x - q3x, v1y = q2y - q3y, v1z = q2z - q3z;
    float a3x = v3x - v2x, a3y = v3y - v2y, a3z = v3z - v2z;
    float a2x = v2x - v1x, a2y = v2y - v1y, a2z = v2z - v1z;
    float jx  = a3x - a2x, jy  = a3y - a2y, jz  = a3z - a2z;
    float nv = sqrtf(((v3x * v3x + v3y * v3y) + v3z * v3z) + 1e-12f);
    float na = sqrtf(((a3x * a3x + a3y * a3y) + a3z * a3z) + 1e-12f);
    float nj = sqrtf(((jx * jx + jy * jy) + jz * jz) + 1e-12f);
    return (nv + 0.6f * na) + 0.35f * nj;
}

__device__ __forceinline__ float energyGuard(int tau,
    float px, float py, float pz,
    float q1x, float q1y, float q1z,
    float q2x, float q2y, float q2z,
    float q3x, float q3y, float q3z)
{
    float v3x = (tau >= 1) ? px - q1x : 0.f, v3y = (tau >= 1) ? py - q1y : 0.f, v3z = (tau >= 1) ? pz - q1z : 0.f;
    float v2x = (tau >= 2) ? q1x - q2x : 0.f, v2y = (tau >= 2) ? q1y - q2y : 0.f, v2z = (tau >= 2) ? q1z - q2z : 0.f;
    float v1x = (tau >= 3) ? q2x - q3x : 0.f, v1y = (tau >= 3) ? q2y - q3y : 0.f, v1z = (tau >= 3) ? q2z - q3z : 0.f;
    float a3x = (tau >= 1) ? v3x - v2x : 0.f, a3y = (tau >= 1) ? v3y - v2y : 0.f, a3z = (tau >= 1) ? v3z - v2z : 0.f;
    float a2x = (tau >= 2) ? v2x - v1x : 0.f, a2y = (tau >= 2) ? v2y - v1y : 0.f, a2z = (tau >= 2) ? v2z - v1z : 0.f;
    float jx  = (tau >= 1) ? a3x - a2x : 0.f, jy  = (tau >= 1) ? a3y - a2y : 0.f, jz  = (tau >= 1) ? a3z - a2z : 0.f;
    float nv = sqrtf(((v3x * v3x + v3y * v3y) + v3z * v3z) + 1e-12f);
    float na = sqrtf(((a3x * a3x + a3y * a3y) + a3z * a3z) + 1e-12f);
    float nj = sqrtf(((jx * jx + jy * jy) + jz * jz) + 1e-12f);
    return (nv + 0.6f * na) + 0.35f * nj;
}

__device__ __forceinline__ float wrapPi(float hd) {
    const float TWO_PI = 6.28318530717958647692f;
    const float INV_TWO_PI = 0.15915494309189533577f;
    return hd - TWO_PI * rintf(hd * INV_TWO_PI);
}

__global__ __launch_bounds__(NT, 2)
void msal_kernel(const float* __restrict__ motion,
                 const int* __restrict__ mask,
                 float* __restrict__ out,
                 int Bn)
{
    extern __shared__ char smem_c[];
    Smem* S = reinterpret_cast<Smem*>(smem_c);

    const int tid = threadIdx.x;
    const int b = blockIdx.x;
    const int t0 = 2 * tid, t1 = t0 + 1;
    const float* src = motion + (long)b * TT * DD;
    const int2 mvp = ((const int2*)(mask + (long)b * TT))[tid];
    const int mv0 = mvp.x, mv1 = mvp.y;
    const float mf0 = mv0 ? 1.0f : 0.0f;
    const float mf1 = mv1 ? 1.0f : 0.0f;

    // ---- stage planes 0..3 (rot_vel, x, z, y) coalesced ----
    #pragma unroll
    for (int i = tid; i < 4 * TT; i += NT) {
        int t = i >> 2, dl = i & 3;
        S->raw[dl][t] = src[(long)t * DD + dl];
    }
    __syncthreads();

    // ---- ang: exclusive cumsum of rot_vel ----
    const float2 rvp = ((const float2*)&S->raw[0][0])[tid];
    const float rv0 = rvp.x, rv1 = rvp.y;
    // xz steps: need t0-1 (odd index -> .y of pair tid-1) and t0 (own .x)
    float vx0 = 0.f, vz0 = 0.f;
    if (tid > 0) {
        vx0 = S->raw[1][t0 - 1];
        vz0 = S->raw[2][t0 - 1];
    }
    const float vx1 = S->raw[1][t0], vz1 = S->raw[2][t0];
    const float2 pyp = ((const float2*)&S->raw[3][0])[tid];
    const float py0r = pyp.x, py1r = pyp.y;

    float ang0, ang1;
    {
        float pair = rv0 + rv1;
        float incl = blockInclScan(pair, S->w1);
        float excl = incl - pair;
        ang0 = excl;
        ang1 = excl + rv0;
    }
    const float qc0 = cosf(ang0), qs0 = sinf(ang0);
    const float qc1 = cosf(ang1), qs1 = sinf(ang1);

    float sx0, sz0, sx1, sz1;
    rotY(qc0, qs0, vx0, vz0, sx0, sz0);
    rotY(qc1, qs1, vx1, vz1, sx1, sz1);
    if (tid == 0) { sx0 = 0.f; sz0 = 0.f; }   // t0=0 has zero step

    float rx0, rz0, rx1, rz1;
    {
        float pairx = sx0 + sx1, pairz = sz0 + sz1;
        __syncthreads();
        float ix = pairx, iz = pairz;
        blockInclScan2(ix, iz, S->w1, S->w2);
        float ex = ix - pairx, ez = iz - pairz;
        rx0 = ex + sx0;         rz0 = ez + sz0;
        rx1 = (ex + sx0) + sx1; rz1 = (ez + sz0) + sz1;
    }

    float h_t1;
    {
        float pv1x = rx1 - rx0, pv1z = rz1 - rz0;
        bool z = (fabsf(pv1x) < 1e-8f) && (fabsf(pv1z) < 1e-8f);
        h_t1 = atan2f(z ? 0.f : pv1z, z ? 1.f : pv1x);
    }
    S->rth[tid] = make_float4(rx1, rz1, h_t1, 0.f);

    // ---- group energies ----
    float S0a = 0.f, S1a = 0.f, S2a = 0.f, S3a = 0.f;
    float S0b = 0.f, S1b = 0.f, S2b = 0.f, S3b = 0.f;

    // joint 0 (root)
    {
        const int buf = 0;
        float px0 = rx0, py0 = py0r, pz0 = rz0;
        float px1 = rx1, py1 = py1r, pz1 = rz1;
        S->px[buf][tid] = make_float2(px0, px1);
        S->py[buf][tid] = make_float2(py0, py1);
        S->pz[buf][tid] = make_float2(pz0, pz1);
        __syncthreads();
        float e0, e1;
        if (tid >= 2) {
            float2 Ax = S->px[buf][tid - 1], Ay = S->py[buf][tid - 1], Az = S->pz[buf][tid - 1];
            float2 Bx = S->px[buf][tid - 2], By = S->py[buf][tid - 2], Bz = S->pz[buf][tid - 2];
            e0 = energyFast(px0, py0, pz0, Ax.y, Ay.y, Az.y, Ax.x, Ay.x, Az.x, Bx.y, By.y, Bz.y);
            e1 = energyFast(px1, py1, pz1, px0, py0, pz0, Ax.y, Ay.y, Az.y, Ax.x, Ay.x, Az.x);
        } else {
            float2 Ax = make_float2(0.f, 0.f), Ay = Ax, Az = Ax;
            if (tid >= 1) { Ax = S->px[buf][tid - 1]; Ay = S->py[buf][tid - 1]; Az = S->pz[buf][tid - 1]; }
            e0 = energyGuard(t0, px0, py0, pz0, Ax.y, Ay.y, Az.y, Ax.x, Ay.x, Az.x, 0.f, 0.f, 0.f);
            e1 = energyGuard(t1, px1, py1, pz1, px0, py0, pz0, Ax.y, Ay.y, Az.y, Ax.x, Ay.x, Az.x);
        }
        S0a += e0; S0b += e1;   // joint 0 is group 0
    }

    // joints 1..21 in 7 chunks of 3
    int j = 1;
    for (int c = 0; c < 7; c++) {
        __syncthreads();   // all reads of previous raw contents complete
        const float* csrc = src + 4 + 9 * c;
        #pragma unroll
        for (int i = tid; i < 9 * TT; i += NT) {
            int t = i / 9, dl = i - 9 * t;
            S->raw[dl][t] = csrc[(long)t * DD + dl];
        }
        __syncthreads();

        #pragma unroll
        for (int jl = 0; jl < 3; jl++, j++) {
            const int buf = j & 1;
            float2 X = ((const float2*)&S->raw[3 * jl    ][0])[tid];
            float2 Y = ((const float2*)&S->raw[3 * jl + 1][0])[tid];
            float2 Z = ((const float2*)&S->raw[3 * jl + 2][0])[tid];
            float ax, az, bx, bz;
            rotY(qc0, qs0, X.x, Z.x, ax, az);
            rotY(qc1, qs1, X.y, Z.y, bx, bz);
            float px0 = ax + rx0, py0 = Y.x, pz0 = az + rz0;
            float px1 = bx + rx1, py1 = Y.y, pz1 = bz + rz1;

            S->px[buf][tid] = make_float2(px0, px1);
            S->py[buf][tid] = make_float2(py0, py1);
            S->pz[buf][tid] = make_float2(pz0, pz1);
            __syncthreads();

            float e0, e1;
            if (tid >= 2) {
                float2 Ax = S->px[buf][tid - 1], Ay = S->py[buf][tid - 1], Az = S->pz[buf][tid - 1];
                float2 Bx = S->px[buf][tid - 2], By = S->py[buf][tid - 2], Bz = S->pz[buf][tid - 2];
                e0 = energyFast(px0, py0, pz0, Ax.y, Ay.y, Az.y, Ax.x, Ay.x, Az.x, Bx.y, By.y, Bz.y);
                e1 = energyFast(px1, py1, pz1, px0, py0, pz0, Ax.y, Ay.y, Az.y, Ax.x, Ay.x, Az.x);
            } else {
                float2 Ax = make_float2(0.f, 0.f), Ay = Ax, Az = Ax;
                if (tid >= 1) { Ax = S->px[buf][tid - 1]; Ay = S->py[buf][tid - 1]; Az = S->pz[buf][tid - 1]; }
                e0 = energyGuard(t0, px0, py0, pz0, Ax.y, Ay.y, Az.y, Ax.x, Ay.x, Az.x, 0.f, 0.f, 0.f);
                e1 = energyGuard(t1, px1, py1, pz1, px0, py0, pz0, Ax.y, Ay.y, Az.y, Ax.x, Ay.x, Az.x);
            }

            int g = c_grp[j];
            if      (g == 0) { S0a += e0; S0b += e1; }
            else if (g == 1) { S1a += e0; S1b += e1; }
            else if (g == 2) { S2a += e0; S2b += e1; }
            else             { S3a += e0; S3b += e1; }
        }
    }

    float Ea = (((1.6f * (S0a / 6.0f) + 1.4f * (S1a / 4.0f)) + 1.2f * (S2a / 8.0f)) + 0.8f * (S3a / 4.0f));
    float Eb = (((1.6f * (S0b / 6.0f) + 1.4f * (S1b / 4.0f)) + 1.2f * (S2b / 8.0f)) + 0.8f * (S3b / 4.0f));

    // ---- turning ----
    float turn0, turn1;
    {
        float rxm1 = 0.f, rzm1 = 0.f, hprev = 0.f;
        if (tid >= 1) {
            float4 rr = S->rth[tid - 1];
            rxm1 = rr.x; rzm1 = rr.y; hprev = rr.z;
        }
        float pv0x = (tid >= 1) ? rx0 - rxm1 : 0.f;
        float pv0z = (tid >= 1) ? rz0 - rzm1 : 0.f;
        bool z = (fabsf(pv0x) < 1e-8f) && (fabsf(pv0z) < 1e-8f);
        float h_t0 = atan2f(z ? 0.f : pv0z, z ? 1.f : pv0x);
        float hd0 = (tid >= 1) ? h_t0 - hprev : 0.f;
        float hd1 = h_t1 - h_t0;
        float wr0 = wrapPi(hd0);
        float wr1 = wrapPi(hd1);
        float pv1x = rx1 - rx0, pv1z = rz1 - rz0;
        turn0 = fabsf(wr0) * sqrtf((pv0x * pv0x + pv0z * pv0z) + 1e-12f);
        turn1 = fabsf(wr1) * sqrtf((pv1x * pv1x + pv1z * pv1z) + 1e-12f);
    }

    float sal0 = (Ea + 1.6f * turn0) * mf0;
    float sal1 = (Eb + 1.6f * turn1) * mf1;

    // ---- normalize by row max ----
    float m = blockReduceMax(fmaxf(sal0, sal1), S->redf);
    m = fmaxf(m, 1e-6f);
    float salN0 = fminf(fmaxf(sal0 / m, 0.0f), 1.0f) * mf0;
    float salN1 = fminf(fmaxf(sal1 / m, 0.0f), 1.0f) * mf1;
    S->sal[tid] = make_float2(salN0, salN1);
    __syncthreads();

    // ---- local max suppression (window 5, pad 2) ----
    float2 L = (tid >= 1)      ? S->sal[tid - 1] : make_float2(-1.f, -1.f);
    float2 R = (tid < NT - 1)  ? S->sal[tid + 1] : make_float2(-1.f, -1.f);
    float lm0 = fmaxf(fmaxf(fmaxf(L.x, L.y), fmaxf(salN0, salN1)), R.x);
    float lm1 = fmaxf(fmaxf(fmaxf(L.y, salN0), fmaxf(salN1, R.x)), R.y);
    float probs0 = salN0 * ((salN0 >= lm0 - 1e-6f) ? 1.0f : 0.0f) * mf0;
    float probs1 = salN1 * ((salN1 >= lm1 - 1e-6f) ? 1.0f : 0.0f) * mf1;
    probs0 = fminf(fmaxf(probs0, 0.0f), 1.0f) * mf0;
    probs1 = fminf(fmaxf(probs1, 0.0f), 1.0f) * mf1;

    // ---- adaptive ST ----
    int n = blockReduceSumI((mv0 ? 1 : 0) + (mv1 ? 1 : 0), S->redi);
    float hv = (n > 0) ? 1.0f : 0.0f;
    int last = ((n > 1) ? n : 1) - 1;
    float ep0 = (t0 == 0 || t0 == last) ? hv : 0.0f;
    float ep1 = (t1 == last) ? hv : 0.0f;
    probs0 = fmaxf(probs0, ep0) * mf0;
    probs1 = fmaxf(probs1, ep1) * mf1;

    float nf = (float)((n > 1) ? n : 1);
    float asum = blockReduceSumF(probs0 * mf0 + probs1 * mf1, S->redf);
    float activity = asum / nf;
    float q = 0.85f + 0.1f * 0.5f - 0.1f * activity;
    q = fminf(fmaxf(q, 0.8f), 0.95f);
    float pos = q * (nf - 1.0f);
    float lof = floorf(pos), hif = ceilf(pos);
    int ilo = (int)lof, ihi = (int)hif;

    // ---- bitonic sort: 1024 elems, 2 per thread ----
    const int i0 = tid, i1 = tid + NT;
    float v0 = mv0 ? probs0 : 2.0f;
    float v1 = mv1 ? probs1 : 2.0f;
    int pb = 0;
    for (int k = 2; k <= TT; k <<= 1) {
        bool up0 = ((i0 & k) == 0);
        bool up1 = ((i1 & k) == 0);
        int j2 = k >> 1;
        if (j2 == NT) {
            float mn = fminf(v0, v1), mx = fmaxf(v0, v1);
            v0 = up0 ? mn : mx;
            v1 = up0 ? mx : mn;
            j2 = NT >> 1;
        }
        for (; j2 >= 32; j2 >>= 1) {
            S->srt[pb][i0] = v0; S->srt[pb][i1] = v1;
            __syncthreads();
            float p0 = S->srt[pb][i0 ^ j2];
            float p1 = S->srt[pb][i1 ^ j2];
            pb ^= 1;
            bool l0 = (i0 & j2) == 0, l1 = (i1 & j2) == 0;
            v0 = (l0 == up0) ? fminf(v0, p0) : fmaxf(v0, p0);
            v1 = (l1 == up1) ? fminf(v1, p1) : fmaxf(v1, p1);
        }
        for (; j2 >= 1; j2 >>= 1) {
            float p0 = __shfl_xor_sync(0xffffffffu, v0, j2);
            float p1 = __shfl_xor_sync(0xffffffffu, v1, j2);
            bool l0 = (i0 & j2) == 0, l1 = (i1 & j2) == 0;
            v0 = (l0 == up0) ? fminf(v0, p0) : fmaxf(v0, p0);
            v1 = (l1 == up1) ? fminf(v1, p1) : fmaxf(v1, p1);
        }
    }
    S->srt[pb][i0] = v0; S->srt[pb][i1] = v1;
    __syncthreads();
    float vlo = S->srt[pb][ilo], vhi = S->srt[pb][ihi];
    float cut = vlo + (pos - lof) * (vhi - vlo);

    float hard0, hard1;
    if (n > 0 && n <= 2)      { hard0 = mf0; hard1 = mf1; }
    else if (n > 2)           { hard0 = (probs0 >= cut) ? 1.0f : 0.0f;
                                hard1 = (probs1 >= cut) ? 1.0f : 0.0f; }
    else                      { hard0 = 0.0f; hard1 = 0.0f; }

    hard0 = fmaxf(hard0, ep0) * mf0;
    hard1 = fmaxf(hard1, ep1) * mf1;
    float pF0 = fmaxf(probs0, ep0) * mf0;
    float pF1 = fmaxf(probs1, ep1) * mf1;
    float st0 = ((hard0 + pF0) - pF0) * mf0;
    float st1 = ((hard1 + pF1) - pF1) * mf1;

    ((float2*)(out + (long)b * TT))[tid] = make_float2(pF0, pF1);
    ((float2*)(out + (long)Bn * TT + (long)b * TT))[tid] = make_float2(st0, st1);
}

extern "C" void kernel_launch(void* const* d_in, const int* in_sizes, int n_in,
                              void* d_out, int out_size) {
    const float* motion = (const float*)d_in[0];
    const int* mask = (const int*)d_in[1];
    float* out = (float*)d_out;
    int Bn = in_sizes[0] / (TT * DD);
    size_t smem_bytes = sizeof(Smem);
    cudaFuncSetAttribute(msal_kernel, cudaFuncAttributeMaxDynamicSharedMemorySize,
                         (int)smem_bytes);
    msal_kernel<<<Bn, NT, smem_bytes>>>(motion, mask, out, Bn);
}